// round 12
// baseline (speedup 1.0000x reference)
#include <cuda_runtime.h>
#include <cuda_bf16.h>
#include <math.h>
#include <stdint.h>

#define NN 10000
#define NE 320000
#define NG 64
#define DD 256

// ---------------- scratch (device globals; no allocation allowed) ----------------
__device__ __align__(16) float d_h[NN * DD];          // node features (current layer)
__device__ __align__(16) __nv_bfloat16 d_ah[NN * DD]; // (h+agg) bf16 hi
__device__ __align__(16) __nv_bfloat16 d_al[NN * DD]; // (h+agg) bf16 lo residual
__device__ __align__(16) __nv_bfloat16 d_whi[5 * 65536]; // W split hi, [l][n][k] K-major
__device__ __align__(16) __nv_bfloat16 d_wlo[5 * 65536]; // W split lo
__device__ int   d_rowstart[NN + 1];
__device__ int   d_cursor[NN];
__device__ int   d_csr[NE];
__device__ int   d_gstart[NG + 1];
__device__ __align__(16) float d_feat[NG * 2 * DD];
__device__ __align__(16) float d_h1[NG * DD];
__device__ __align__(16) float d_h2[NG * 64];
__device__ int   d_is64;

// ---------------- helpers ----------------
__device__ __forceinline__ uint32_t smem_u32(const void* p) {
    uint32_t a;
    asm("{ .reg .u64 t; cvta.to.shared.u64 t, %1; cvt.u32.u64 %0, t; }" : "=r"(a) : "l"(p));
    return a;
}
#define SW128(o) ((o) ^ (((o) >> 3) & 0x70))

__device__ __forceinline__ void ldm_x4(uint32_t* r, uint32_t addr) {
    asm volatile("ldmatrix.sync.aligned.m8n8.x4.shared.b16 {%0,%1,%2,%3}, [%4];"
        : "=r"(r[0]), "=r"(r[1]), "=r"(r[2]), "=r"(r[3]) : "r"(addr));
}
__device__ __forceinline__ void mma_bf16(float* c, const uint32_t* a, const uint32_t* b) {
    asm volatile("mma.sync.aligned.m16n8k16.row.col.f32.bf16.bf16.f32 "
        "{%0,%1,%2,%3}, {%4,%5,%6,%7}, {%8,%9}, {%0,%1,%2,%3};"
        : "+f"(c[0]), "+f"(c[1]), "+f"(c[2]), "+f"(c[3])
        : "r"(a[0]), "r"(a[1]), "r"(a[2]), "r"(a[3]), "r"(b[0]), "r"(b[1]));
}

// index loader honoring detected dtype
__device__ __forceinline__ long long load_idx(const void* p, long long i, int is64) {
    if (is64) return ((const long long*)p)[i];
    return (long long)((const int*)p)[i];
}

// ---------------- dtype detection ----------------
__global__ void detect_kernel(const void* __restrict__ ei) {
    if (threadIdx.x == 0 && blockIdx.x == 0) {
        const long long* p = (const long long*)ei;
        int ok = 1;
        for (int i = 0; i < 64; i++) {
            long long v = p[i];
            if (v < 0 || v >= NN) { ok = 0; break; }
        }
        d_is64 = ok;
    }
}

// ---------------- init ----------------
__global__ void copy_x_kernel(const float* __restrict__ x) {
    int i = blockIdx.x * blockDim.x + threadIdx.x;
    if (i < NN * DD / 4) ((float4*)d_h)[i] = ((const float4*)x)[i];
}

__global__ void zero_rs_kernel() {
    int i = blockIdx.x * blockDim.x + threadIdx.x;
    if (i <= NN) d_rowstart[i] = 0;
}

// ---------------- weight split: Whi/Wlo[l][n][k] = split(W_l[k][n]) ----------------
__global__ void wsplit_kernel(const float* __restrict__ w0, const float* __restrict__ w1,
                              const float* __restrict__ w2, const float* __restrict__ w3,
                              const float* __restrict__ w4) {
    int idx = blockIdx.x * blockDim.x + threadIdx.x;
    if (idx >= 5 * 65536) return;
    int l = idx >> 16;
    int rem = idx & 65535;
    int n = rem >> 8;
    int k = rem & 255;
    const float* W = (l == 0) ? w0 : (l == 1) ? w1 : (l == 2) ? w2 : (l == 3) ? w3 : w4;
    float v = W[k * 256 + n];
    __nv_bfloat16 hi = __float2bfloat16(v);
    d_whi[idx] = hi;
    d_wlo[idx] = __float2bfloat16(v - __bfloat162float(hi));
}

// ---------------- CSR build (keyed by dst) ----------------
__global__ void hist_kernel(const void* __restrict__ ei) {
    int e = blockIdx.x * blockDim.x + threadIdx.x;
    if (e < NE) {
        int is64 = d_is64;
        int dn = (int)load_idx(ei, (long long)NE + e, is64);
        if (dn >= 0 && dn < NN) atomicAdd(&d_rowstart[dn + 1], 1);
    }
}

__global__ void scan_kernel() {
    __shared__ int sp[1024];
    const int CH = 10;
    int t = threadIdx.x;
    int base = t * CH;
    int v[CH];
    int run = 0;
#pragma unroll
    for (int j = 0; j < CH; j++) {
        int idx = base + j;
        int xv = (idx <= NN) ? d_rowstart[idx] : 0;
        run += xv;
        v[j] = run;
    }
    sp[t] = run;
    __syncthreads();
    for (int off = 1; off < 1024; off <<= 1) {
        int add = (t >= off) ? sp[t - off] : 0;
        __syncthreads();
        sp[t] += add;
        __syncthreads();
    }
    int excl = (t > 0) ? sp[t - 1] : 0;
#pragma unroll
    for (int j = 0; j < CH; j++) {
        int idx = base + j;
        if (idx <= NN) {
            int val = v[j] + excl;
            d_rowstart[idx] = val;
            if (idx < NN) d_cursor[idx] = val;
        }
    }
}

__global__ void fill_kernel(const void* __restrict__ ei) {
    int e = blockIdx.x * blockDim.x + threadIdx.x;
    if (e < NE) {
        int is64 = d_is64;
        int sn = (int)load_idx(ei, e, is64);
        int dn = (int)load_idx(ei, (long long)NE + e, is64);
        if (dn >= 0 && dn < NN && sn >= 0 && sn < NN) {
            int slot = atomicAdd(&d_cursor[dn], 1);
            if (slot < NE) d_csr[slot] = sn;
        }
    }
}

// ---------------- aggregation: split(h[i] + sum_{j in N(i)} h[j]) -> d_ah/d_al ----------------
__device__ __forceinline__ void split4_store(__nv_bfloat16* hp, __nv_bfloat16* lp, float4 v) {
    float f[4] = {v.x, v.y, v.z, v.w};
    __nv_bfloat16 h[4], l[4];
#pragma unroll
    for (int i = 0; i < 4; i++) {
        h[i] = __float2bfloat16(f[i]);
        l[i] = __float2bfloat16(f[i] - __bfloat162float(h[i]));
    }
    *(uint2*)hp = *(uint2*)h;
    *(uint2*)lp = *(uint2*)l;
}

__global__ void agg_kernel() {
    int warp = (blockIdx.x * blockDim.x + threadIdx.x) >> 5;
    int lane = threadIdx.x & 31;
    if (warp >= NN) return;
    int beg = d_rowstart[warp];
    int end = d_rowstart[warp + 1];
    const float4* self = (const float4*)(d_h + (size_t)warp * DD);
    float4 a0 = self[lane];
    float4 a1 = self[lane + 32];
    for (int e = beg; e < end; e++) {
        int s = d_csr[e];
        const float4* r = (const float4*)(d_h + (size_t)s * DD);
        float4 b0 = r[lane];
        float4 b1 = r[lane + 32];
        a0.x += b0.x; a0.y += b0.y; a0.z += b0.z; a0.w += b0.w;
        a1.x += b1.x; a1.y += b1.y; a1.z += b1.z; a1.w += b1.w;
    }
    size_t base = (size_t)warp * DD;
    split4_store(d_ah + base + lane * 4, d_al + base + lane * 4, a0);
    split4_store(d_ah + base + 128 + lane * 4, d_al + base + 128 + lane * 4, a1);
}

// ---------------- bf16 mma.sync GEMM: d_h = relu((Ah+Al)@(Wh+Wl) + b) ----------------
// CTA 128x128, 8 warps (4x2), warp tile 32x64. K=256 in 4 chunks of 64.
// SMEM tiles: 128 rows x 64 bf16 (128B rows, SW128 swizzle).
#define SA_H 0
#define SA_L 16384
#define SB_H 32768
#define SB_L 49152
#define GEMM_SMEM 65536

__global__ void __launch_bounds__(256, 1) mma_gemm_kernel(const float* __restrict__ bias,
                                                          int layer) {
    extern __shared__ char smem[];
    const uint32_t sb = smem_u32(smem);
    const int tid = threadIdx.x, lane = tid & 31, wid = tid >> 5;
    const int m0 = blockIdx.x * 128, n0 = blockIdx.y * 128;
    const int wm = (wid & 3) * 32;   // warp row base within tile
    const int wn = (wid >> 2) * 64;  // warp col base within tile
    const __nv_bfloat16* wh = d_whi + (size_t)layer * 65536;
    const __nv_bfloat16* wl = d_wlo + (size_t)layer * 65536;

    float acc[2][8][4];
#pragma unroll
    for (int mt = 0; mt < 2; mt++)
#pragma unroll
        for (int nt = 0; nt < 8; nt++)
#pragma unroll
            for (int j = 0; j < 4; j++) acc[mt][nt][j] = 0.f;

    for (int c = 0; c < 4; c++) {
        // A tiles (hi/lo): 128 rows x 64 bf16 = 1024 uint4, 4 per thread
#pragma unroll
        for (int i = 0; i < 4; i++) {
            int idx = i * 256 + tid;
            int row = idx >> 3, q = idx & 7;
            int gr = m0 + row;
            uint4 vh = make_uint4(0, 0, 0, 0), vl = make_uint4(0, 0, 0, 0);
            if (gr < NN) {
                vh = *(const uint4*)(d_ah + (size_t)gr * 256 + c * 64 + q * 8);
                vl = *(const uint4*)(d_al + (size_t)gr * 256 + c * 64 + q * 8);
            }
            uint32_t off = SW128((uint32_t)(row * 128 + q * 16));
            *(uint4*)(smem + SA_H + off) = vh;
            *(uint4*)(smem + SA_L + off) = vl;
        }
        // B tiles (hi/lo): rows n0..n0+127 of W[n][k]
#pragma unroll
        for (int i = 0; i < 4; i++) {
            int idx = i * 256 + tid;
            int row = idx >> 3, q = idx & 7;
            int gn = n0 + row;
            uint4 vh = *(const uint4*)(wh + (size_t)gn * 256 + c * 64 + q * 8);
            uint4 vl = *(const uint4*)(wl + (size_t)gn * 256 + c * 64 + q * 8);
            uint32_t off = SW128((uint32_t)(row * 128 + q * 16));
            *(uint4*)(smem + SB_H + off) = vh;
            *(uint4*)(smem + SB_L + off) = vl;
        }
        __syncthreads();

#pragma unroll
        for (int ks = 0; ks < 4; ks++) {
            const int k0 = ks * 16;
            uint32_t ah[2][4], al[2][4], bh[4][4], bl[4][4];
#pragma unroll
            for (int mt = 0; mt < 2; mt++) {
                int r = wm + mt * 16 + (lane & 15);
                int kb = (k0 + ((lane >> 4) << 3)) * 2;
                uint32_t off = SW128((uint32_t)(r * 128 + kb));
                ldm_x4(ah[mt], sb + SA_H + off);
                ldm_x4(al[mt], sb + SA_L + off);
            }
#pragma unroll
            for (int np = 0; np < 4; np++) {
                int r = wn + np * 16 + ((lane >> 4) << 3) + (lane & 7);
                int kb = (k0 + (((lane >> 3) & 1) << 3)) * 2;
                uint32_t off = SW128((uint32_t)(r * 128 + kb));
                ldm_x4(bh[np], sb + SB_H + off);
                ldm_x4(bl[np], sb + SB_L + off);
            }
#pragma unroll
            for (int mt = 0; mt < 2; mt++)
#pragma unroll
                for (int nt = 0; nt < 8; nt++) {
                    const uint32_t* B0 = &bh[nt >> 1][(nt & 1) * 2];
                    const uint32_t* B1 = &bl[nt >> 1][(nt & 1) * 2];
                    mma_bf16(acc[mt][nt], ah[mt], B0);
                    mma_bf16(acc[mt][nt], ah[mt], B1);
                    mma_bf16(acc[mt][nt], al[mt], B0);
                }
        }
        __syncthreads();
    }

    // epilogue: c0,c1 at (row t/4, col (t%4)*2), c2,c3 at row t/4+8
    const int tq = lane >> 2;
    const int tr = (lane & 3) * 2;
#pragma unroll
    for (int mt = 0; mt < 2; mt++)
#pragma unroll
        for (int nt = 0; nt < 8; nt++) {
            int gc = n0 + wn + nt * 8 + tr;
            float2 bv = *(const float2*)(bias + gc);
            int gr0 = m0 + wm + mt * 16 + tq;
            if (gr0 < NN) {
                float2 o;
                o.x = fmaxf(acc[mt][nt][0] + bv.x, 0.f);
                o.y = fmaxf(acc[mt][nt][1] + bv.y, 0.f);
                *(float2*)(d_h + (size_t)gr0 * 256 + gc) = o;
            }
            int gr1 = gr0 + 8;
            if (gr1 < NN) {
                float2 o;
                o.x = fmaxf(acc[mt][nt][2] + bv.x, 0.f);
                o.y = fmaxf(acc[mt][nt][3] + bv.y, 0.f);
                *(float2*)(d_h + (size_t)gr1 * 256 + gc) = o;
            }
        }
}

// ---------------- pooling ----------------
__global__ void bounds_kernel(const void* __restrict__ batch) {
    int g = threadIdx.x;
    if (g > NG) return;
    int is64 = d_is64;
    int lo = 0, hi = NN;
    while (lo < hi) {
        int mid = (lo + hi) >> 1;
        if (load_idx(batch, mid, is64) < (long long)g) lo = mid + 1;
        else hi = mid;
    }
    d_gstart[g] = lo;
}

__global__ void pool_kernel() {
    int g = blockIdx.x;
    int c = threadIdx.x;
    int s = d_gstart[g], e = d_gstart[g + 1];
    float sum = 0.f;
    float mx = -INFINITY;
    for (int i = s; i < e; i++) {
        float v = d_h[(size_t)i * DD + c];
        sum += v;
        mx = fmaxf(mx, v);
    }
    int cnt = e - s;
    float denom = fmaxf((float)cnt, 1.0f);
    d_feat[g * 512 + c] = sum / denom;
    d_feat[g * 512 + 256 + c] = mx;
}

// ---------------- head MLP ----------------
__global__ void head1_kernel(const float* __restrict__ w, const float* __restrict__ b) {
    __shared__ float s[512];
    int g = blockIdx.x;
    for (int i = threadIdx.x; i < 512; i += 256) s[i] = d_feat[g * 512 + i];
    __syncthreads();
    int t = threadIdx.x;
    float acc = b[t];
    for (int k = 0; k < 512; k++) acc = fmaf(s[k], w[k * 256 + t], acc);
    d_h1[g * 256 + t] = fmaxf(acc, 0.f);
}

__global__ void head2_kernel(const float* __restrict__ w, const float* __restrict__ b) {
    __shared__ float s[256];
    int g = blockIdx.x;
    for (int i = threadIdx.x; i < 256; i += 64) s[i] = d_h1[g * 256 + i];
    __syncthreads();
    int t = threadIdx.x;
    float acc = b[t];
    for (int k = 0; k < 256; k++) acc = fmaf(s[k], w[k * 64 + t], acc);
    d_h2[g * 64 + t] = fmaxf(acc, 0.f);
}

__global__ void head3_kernel(const float* __restrict__ w, const float* __restrict__ b,
                             float* __restrict__ out) {
    int g = threadIdx.x;
    if (g >= NG) return;
    float acc = b[0];
    for (int k = 0; k < 64; k++) acc = fmaf(d_h2[g * 64 + k], w[k], acc);
    out[g] = 1.0f / (1.0f + expf(-acc));
}

// ---------------- launch ----------------
extern "C" void kernel_launch(void* const* d_in, const int* in_sizes, int n_in,
                              void* d_out, int out_size) {
    const float* x = (const float*)d_in[0];
    const void* ei = d_in[1];
    const void* batch = d_in[2];
    const float* w[5];
    const float* b[5];
    for (int i = 0; i < 5; i++) {
        w[i] = (const float*)d_in[3 + 2 * i];
        b[i] = (const float*)d_in[4 + 2 * i];
    }
    const float* wl1 = (const float*)d_in[13];
    const float* bl1 = (const float*)d_in[14];
    const float* wl2 = (const float*)d_in[15];
    const float* bl2 = (const float*)d_in[16];
    const float* wl3 = (const float*)d_in[17];
    const float* bl3 = (const float*)d_in[18];
    float* out = (float*)d_out;

    static int configured = 0;
    if (!configured) {
        cudaFuncSetAttribute(mma_gemm_kernel, cudaFuncAttributeMaxDynamicSharedMemorySize,
                             GEMM_SMEM);
        configured = 1;
    }

    detect_kernel<<<1, 32>>>(ei);
    copy_x_kernel<<<(NN * DD / 4 + 255) / 256, 256>>>(x);
    zero_rs_kernel<<<(NN + 1 + 255) / 256, 256>>>();
    hist_kernel<<<(NE + 255) / 256, 256>>>(ei);
    scan_kernel<<<1, 1024>>>();
    fill_kernel<<<(NE + 255) / 256, 256>>>(ei);
    wsplit_kernel<<<(5 * 65536 + 255) / 256, 256>>>(w[0], w[1], w[2], w[3], w[4]);

    for (int l = 0; l < 5; l++) {
        agg_kernel<<<(NN * 32 + 255) / 256, 256>>>();
        mma_gemm_kernel<<<dim3((NN + 127) / 128, 2), 256, GEMM_SMEM>>>(b[l], l);
    }

    bounds_kernel<<<1, 128>>>(batch);
    pool_kernel<<<NG, 256>>>();
    head1_kernel<<<NG, 256>>>(wl1, bl1);
    head2_kernel<<<NG, 64>>>(wl2, bl2);
    head3_kernel<<<1, 64>>>(wl3, bl3, out);
}

// round 14
// speedup vs baseline: 1.0129x; 1.0129x over previous
#include <cuda_runtime.h>
#include <cuda_bf16.h>
#include <math.h>
#include <stdint.h>

#define NN 10000
#define NE 320000
#define NG 64
#define DD 256

// ---------------- scratch (device globals; no allocation allowed) ----------------
__device__ __align__(16) float d_h[NN * DD];          // node features (current layer)
__device__ __align__(16) __nv_bfloat16 d_ah[NN * DD]; // (h+agg) bf16 hi
__device__ __align__(16) __nv_bfloat16 d_al[NN * DD]; // (h+agg) bf16 lo residual
__device__ __align__(16) __nv_bfloat16 d_whi[5 * 65536]; // W split hi, [l][n][k] K-major
__device__ __align__(16) __nv_bfloat16 d_wlo[5 * 65536]; // W split lo
__device__ int   d_rowstart[NN + 1];
__device__ int   d_cursor[NN];
__device__ int   d_csr[NE];
__device__ int   d_gstart[NG + 1];
__device__ __align__(16) float d_feat[NG * 2 * DD];
__device__ __align__(16) float d_h1[NG * DD];
__device__ __align__(16) float d_h2[NG * 64];
__device__ int   d_is64;

// ---------------- helpers ----------------
__device__ __forceinline__ uint32_t smem_u32(const void* p) {
    uint32_t a;
    asm("{ .reg .u64 t; cvta.to.shared.u64 t, %1; cvt.u32.u64 %0, t; }" : "=r"(a) : "l"(p));
    return a;
}
#define SW128(o) ((o) ^ (((o) >> 3) & 0x70))

__device__ __forceinline__ void ldm_x4(uint32_t* r, uint32_t addr) {
    asm volatile("ldmatrix.sync.aligned.m8n8.x4.shared.b16 {%0,%1,%2,%3}, [%4];"
        : "=r"(r[0]), "=r"(r[1]), "=r"(r[2]), "=r"(r[3]) : "r"(addr));
}
__device__ __forceinline__ void mma_bf16(float* c, const uint32_t* a, const uint32_t* b) {
    asm volatile("mma.sync.aligned.m16n8k16.row.col.f32.bf16.bf16.f32 "
        "{%0,%1,%2,%3}, {%4,%5,%6,%7}, {%8,%9}, {%0,%1,%2,%3};"
        : "+f"(c[0]), "+f"(c[1]), "+f"(c[2]), "+f"(c[3])
        : "r"(a[0]), "r"(a[1]), "r"(a[2]), "r"(a[3]), "r"(b[0]), "r"(b[1]));
}

// index loader honoring detected dtype
__device__ __forceinline__ long long load_idx(const void* p, long long i, int is64) {
    if (is64) return ((const long long*)p)[i];
    return (long long)((const int*)p)[i];
}

// ---------------- dtype detection ----------------
__global__ void detect_kernel(const void* __restrict__ ei) {
    if (threadIdx.x == 0 && blockIdx.x == 0) {
        const long long* p = (const long long*)ei;
        int ok = 1;
        for (int i = 0; i < 64; i++) {
            long long v = p[i];
            if (v < 0 || v >= NN) { ok = 0; break; }
        }
        d_is64 = ok;
    }
}

// ---------------- init ----------------
__global__ void copy_x_kernel(const float* __restrict__ x) {
    int i = blockIdx.x * blockDim.x + threadIdx.x;
    if (i < NN * DD / 4) ((float4*)d_h)[i] = ((const float4*)x)[i];
}

__global__ void zero_rs_kernel() {
    int i = blockIdx.x * blockDim.x + threadIdx.x;
    if (i <= NN) d_rowstart[i] = 0;
}

// ---------------- weight split: Whi/Wlo[l][n][k] = split(W_l[k][n]) ----------------
__global__ void wsplit_kernel(const float* __restrict__ w0, const float* __restrict__ w1,
                              const float* __restrict__ w2, const float* __restrict__ w3,
                              const float* __restrict__ w4) {
    int idx = blockIdx.x * blockDim.x + threadIdx.x;
    if (idx >= 5 * 65536) return;
    int l = idx >> 16;
    int rem = idx & 65535;
    int n = rem >> 8;
    int k = rem & 255;
    const float* W = (l == 0) ? w0 : (l == 1) ? w1 : (l == 2) ? w2 : (l == 3) ? w3 : w4;
    float v = W[k * 256 + n];
    __nv_bfloat16 hi = __float2bfloat16(v);
    d_whi[idx] = hi;
    d_wlo[idx] = __float2bfloat16(v - __bfloat162float(hi));
}

// ---------------- CSR build (keyed by dst) ----------------
__global__ void hist_kernel(const void* __restrict__ ei) {
    int e = blockIdx.x * blockDim.x + threadIdx.x;
    if (e < NE) {
        int is64 = d_is64;
        int dn = (int)load_idx(ei, (long long)NE + e, is64);
        if (dn >= 0 && dn < NN) atomicAdd(&d_rowstart[dn + 1], 1);
    }
}

__global__ void scan_kernel() {
    __shared__ int sp[1024];
    const int CH = 10;
    int t = threadIdx.x;
    int base = t * CH;
    int v[CH];
    int run = 0;
#pragma unroll
    for (int j = 0; j < CH; j++) {
        int idx = base + j;
        int xv = (idx <= NN) ? d_rowstart[idx] : 0;
        run += xv;
        v[j] = run;
    }
    sp[t] = run;
    __syncthreads();
    for (int off = 1; off < 1024; off <<= 1) {
        int add = (t >= off) ? sp[t - off] : 0;
        __syncthreads();
        sp[t] += add;
        __syncthreads();
    }
    int excl = (t > 0) ? sp[t - 1] : 0;
#pragma unroll
    for (int j = 0; j < CH; j++) {
        int idx = base + j;
        if (idx <= NN) {
            int val = v[j] + excl;
            d_rowstart[idx] = val;
            if (idx < NN) d_cursor[idx] = val;
        }
    }
}

__global__ void fill_kernel(const void* __restrict__ ei) {
    int e = blockIdx.x * blockDim.x + threadIdx.x;
    if (e < NE) {
        int is64 = d_is64;
        int sn = (int)load_idx(ei, e, is64);
        int dn = (int)load_idx(ei, (long long)NE + e, is64);
        if (dn >= 0 && dn < NN && sn >= 0 && sn < NN) {
            int slot = atomicAdd(&d_cursor[dn], 1);
            if (slot < NE) d_csr[slot] = sn;
        }
    }
}

// ---------------- aggregation: split(h[i] + sum_{j in N(i)} h[j]) -> d_ah/d_al ----------------
// One warp per node (proven-clean R4 structure); edge loop unrolled x2 in place
// for 4 independent LDG.128 chains per iteration.
__device__ __forceinline__ void split4_store(__nv_bfloat16* hp, __nv_bfloat16* lp, float4 v) {
    float f[4] = {v.x, v.y, v.z, v.w};
    __nv_bfloat16 h[4], l[4];
#pragma unroll
    for (int i = 0; i < 4; i++) {
        h[i] = __float2bfloat16(f[i]);
        l[i] = __float2bfloat16(f[i] - __bfloat162float(h[i]));
    }
    *(uint2*)hp = *(uint2*)h;
    *(uint2*)lp = *(uint2*)l;
}

__global__ void agg_kernel() {
    int warp = (blockIdx.x * blockDim.x + threadIdx.x) >> 5;
    int lane = threadIdx.x & 31;
    if (warp >= NN) return;
    int beg = d_rowstart[warp];
    int end = d_rowstart[warp + 1];
    const float4* self = (const float4*)(d_h + (size_t)warp * DD);
    float4 a0 = self[lane];
    float4 a1 = self[lane + 32];
    int e = beg;
    for (; e + 2 <= end; e += 2) {
        int s0 = d_csr[e];
        int s1 = d_csr[e + 1];
        const float4* r0 = (const float4*)(d_h + (size_t)s0 * DD);
        const float4* r1 = (const float4*)(d_h + (size_t)s1 * DD);
        float4 b0 = r0[lane];
        float4 c0 = r1[lane];
        float4 b1 = r0[lane + 32];
        float4 c1 = r1[lane + 32];
        a0.x += b0.x + c0.x; a0.y += b0.y + c0.y; a0.z += b0.z + c0.z; a0.w += b0.w + c0.w;
        a1.x += b1.x + c1.x; a1.y += b1.y + c1.y; a1.z += b1.z + c1.z; a1.w += b1.w + c1.w;
    }
    for (; e < end; e++) {
        int s = d_csr[e];
        const float4* r = (const float4*)(d_h + (size_t)s * DD);
        float4 b0 = r[lane];
        float4 b1 = r[lane + 32];
        a0.x += b0.x; a0.y += b0.y; a0.z += b0.z; a0.w += b0.w;
        a1.x += b1.x; a1.y += b1.y; a1.z += b1.z; a1.w += b1.w;
    }
    size_t base = (size_t)warp * DD;
    split4_store(d_ah + base + lane * 4, d_al + base + lane * 4, a0);
    split4_store(d_ah + base + 128 + lane * 4, d_al + base + 128 + lane * 4, a1);
}

// ---------------- bf16 mma.sync GEMM: d_h = relu((Ah+Al)@(Wh+Wl) + b) ----------------
// CTA 128x128, 8 warps (4x2), warp tile 32x64. K=256 in 4 chunks of 64.
// SMEM tiles: 128 rows x 64 bf16 (128B rows, SW128 swizzle).
// UNCHANGED from the R4/R12 passing binary.
#define SA_H 0
#define SA_L 16384
#define SB_H 32768
#define SB_L 49152
#define GEMM_SMEM 65536

__global__ void __launch_bounds__(256, 1) mma_gemm_kernel(const float* __restrict__ bias,
                                                          int layer) {
    extern __shared__ char smem[];
    const uint32_t sb = smem_u32(smem);
    const int tid = threadIdx.x, lane = tid & 31, wid = tid >> 5;
    const int m0 = blockIdx.x * 128, n0 = blockIdx.y * 128;
    const int wm = (wid & 3) * 32;   // warp row base within tile
    const int wn = (wid >> 2) * 64;  // warp col base within tile
    const __nv_bfloat16* wh = d_whi + (size_t)layer * 65536;
    const __nv_bfloat16* wl = d_wlo + (size_t)layer * 65536;

    float acc[2][8][4];
#pragma unroll
    for (int mt = 0; mt < 2; mt++)
#pragma unroll
        for (int nt = 0; nt < 8; nt++)
#pragma unroll
            for (int j = 0; j < 4; j++) acc[mt][nt][j] = 0.f;

    for (int c = 0; c < 4; c++) {
        // A tiles (hi/lo): 128 rows x 64 bf16 = 1024 uint4, 4 per thread
#pragma unroll
        for (int i = 0; i < 4; i++) {
            int idx = i * 256 + tid;
            int row = idx >> 3, q = idx & 7;
            int gr = m0 + row;
            uint4 vh = make_uint4(0, 0, 0, 0), vl = make_uint4(0, 0, 0, 0);
            if (gr < NN) {
                vh = *(const uint4*)(d_ah + (size_t)gr * 256 + c * 64 + q * 8);
                vl = *(const uint4*)(d_al + (size_t)gr * 256 + c * 64 + q * 8);
            }
            uint32_t off = SW128((uint32_t)(row * 128 + q * 16));
            *(uint4*)(smem + SA_H + off) = vh;
            *(uint4*)(smem + SA_L + off) = vl;
        }
        // B tiles (hi/lo): rows n0..n0+127 of W[n][k]
#pragma unroll
        for (int i = 0; i < 4; i++) {
            int idx = i * 256 + tid;
            int row = idx >> 3, q = idx & 7;
            int gn = n0 + row;
            uint4 vh = *(const uint4*)(wh + (size_t)gn * 256 + c * 64 + q * 8);
            uint4 vl = *(const uint4*)(wl + (size_t)gn * 256 + c * 64 + q * 8);
            uint32_t off = SW128((uint32_t)(row * 128 + q * 16));
            *(uint4*)(smem + SB_H + off) = vh;
            *(uint4*)(smem + SB_L + off) = vl;
        }
        __syncthreads();

#pragma unroll
        for (int ks = 0; ks < 4; ks++) {
            const int k0 = ks * 16;
            uint32_t ah[2][4], al[2][4], bh[4][4], bl[4][4];
#pragma unroll
            for (int mt = 0; mt < 2; mt++) {
                int r = wm + mt * 16 + (lane & 15);
                int kb = (k0 + ((lane >> 4) << 3)) * 2;
                uint32_t off = SW128((uint32_t)(r * 128 + kb));
                ldm_x4(ah[mt], sb + SA_H + off);
                ldm_x4(al[mt], sb + SA_L + off);
            }
#pragma unroll
            for (int np = 0; np < 4; np++) {
                int r = wn + np * 16 + ((lane >> 4) << 3) + (lane & 7);
                int kb = (k0 + (((lane >> 3) & 1) << 3)) * 2;
                uint32_t off = SW128((uint32_t)(r * 128 + kb));
                ldm_x4(bh[np], sb + SB_H + off);
                ldm_x4(bl[np], sb + SB_L + off);
            }
#pragma unroll
            for (int mt = 0; mt < 2; mt++)
#pragma unroll
                for (int nt = 0; nt < 8; nt++) {
                    const uint32_t* B0 = &bh[nt >> 1][(nt & 1) * 2];
                    const uint32_t* B1 = &bl[nt >> 1][(nt & 1) * 2];
                    mma_bf16(acc[mt][nt], ah[mt], B0);
                    mma_bf16(acc[mt][nt], ah[mt], B1);
                    mma_bf16(acc[mt][nt], al[mt], B0);
                }
        }
        __syncthreads();
    }

    // epilogue: c0,c1 at (row t/4, col (t%4)*2), c2,c3 at row t/4+8
    const int tq = lane >> 2;
    const int tr = (lane & 3) * 2;
#pragma unroll
    for (int mt = 0; mt < 2; mt++)
#pragma unroll
        for (int nt = 0; nt < 8; nt++) {
            int gc = n0 + wn + nt * 8 + tr;
            float2 bv = *(const float2*)(bias + gc);
            int gr0 = m0 + wm + mt * 16 + tq;
            if (gr0 < NN) {
                float2 o;
                o.x = fmaxf(acc[mt][nt][0] + bv.x, 0.f);
                o.y = fmaxf(acc[mt][nt][1] + bv.y, 0.f);
                *(float2*)(d_h + (size_t)gr0 * 256 + gc) = o;
            }
            int gr1 = gr0 + 8;
            if (gr1 < NN) {
                float2 o;
                o.x = fmaxf(acc[mt][nt][2] + bv.x, 0.f);
                o.y = fmaxf(acc[mt][nt][3] + bv.y, 0.f);
                *(float2*)(d_h + (size_t)gr1 * 256 + gc) = o;
            }
        }
}

// ---------------- pooling ----------------
__global__ void bounds_kernel(const void* __restrict__ batch) {
    int g = threadIdx.x;
    if (g > NG) return;
    int is64 = d_is64;
    int lo = 0, hi = NN;
    while (lo < hi) {
        int mid = (lo + hi) >> 1;
        if (load_idx(batch, mid, is64) < (long long)g) lo = mid + 1;
        else hi = mid;
    }
    d_gstart[g] = lo;
}

__global__ void pool_kernel() {
    int g = blockIdx.x;
    int c = threadIdx.x;
    int s = d_gstart[g], e = d_gstart[g + 1];
    float sum = 0.f;
    float mx = -INFINITY;
    for (int i = s; i < e; i++) {
        float v = d_h[(size_t)i * DD + c];
        sum += v;
        mx = fmaxf(mx, v);
    }
    int cnt = e - s;
    float denom = fmaxf((float)cnt, 1.0f);
    d_feat[g * 512 + c] = sum / denom;
    d_feat[g * 512 + 256 + c] = mx;
}

// ---------------- head MLP ----------------
__global__ void head1_kernel(const float* __restrict__ w, const float* __restrict__ b) {
    __shared__ float s[512];
    int g = blockIdx.x;
    for (int i = threadIdx.x; i < 512; i += 256) s[i] = d_feat[g * 512 + i];
    __syncthreads();
    int t = threadIdx.x;
    float acc = b[t];
    for (int k = 0; k < 512; k++) acc = fmaf(s[k], w[k * 256 + t], acc);
    d_h1[g * 256 + t] = fmaxf(acc, 0.f);
}

__global__ void head2_kernel(const float* __restrict__ w, const float* __restrict__ b) {
    __shared__ float s[256];
    int g = blockIdx.x;
    for (int i = threadIdx.x; i < 256; i += 64) s[i] = d_h1[g * 256 + i];
    __syncthreads();
    int t = threadIdx.x;
    float acc = b[t];
    for (int k = 0; k < 256; k++) acc = fmaf(s[k], w[k * 64 + t], acc);
    d_h2[g * 64 + t] = fmaxf(acc, 0.f);
}

__global__ void head3_kernel(const float* __restrict__ w, const float* __restrict__ b,
                             float* __restrict__ out) {
    int g = threadIdx.x;
    if (g >= NG) return;
    float acc = b[0];
    for (int k = 0; k < 64; k++) acc = fmaf(d_h2[g * 64 + k], w[k], acc);
    out[g] = 1.0f / (1.0f + expf(-acc));
}

// ---------------- launch ----------------
extern "C" void kernel_launch(void* const* d_in, const int* in_sizes, int n_in,
                              void* d_out, int out_size) {
    const float* x = (const float*)d_in[0];
    const void* ei = d_in[1];
    const void* batch = d_in[2];
    const float* w[5];
    const float* b[5];
    for (int i = 0; i < 5; i++) {
        w[i] = (const float*)d_in[3 + 2 * i];
        b[i] = (const float*)d_in[4 + 2 * i];
    }
    const float* wl1 = (const float*)d_in[13];
    const float* bl1 = (const float*)d_in[14];
    const float* wl2 = (const float*)d_in[15];
    const float* bl2 = (const float*)d_in[16];
    const float* wl3 = (const float*)d_in[17];
    const float* bl3 = (const float*)d_in[18];
    float* out = (float*)d_out;

    static int configured = 0;
    if (!configured) {
        cudaFuncSetAttribute(mma_gemm_kernel, cudaFuncAttributeMaxDynamicSharedMemorySize,
                             GEMM_SMEM);
        configured = 1;
    }

    detect_kernel<<<1, 32>>>(ei);
    copy_x_kernel<<<(NN * DD / 4 + 255) / 256, 256>>>(x);
    zero_rs_kernel<<<(NN + 1 + 255) / 256, 256>>>();
    hist_kernel<<<(NE + 255) / 256, 256>>>(ei);
    scan_kernel<<<1, 1024>>>();
    fill_kernel<<<(NE + 255) / 256, 256>>>(ei);
    wsplit_kernel<<<(5 * 65536 + 255) / 256, 256>>>(w[0], w[1], w[2], w[3], w[4]);

    for (int l = 0; l < 5; l++) {
        agg_kernel<<<(NN * 32 + 255) / 256, 256>>>();
        mma_gemm_kernel<<<dim3((NN + 127) / 128, 2), 256, GEMM_SMEM>>>(b[l], l);
    }

    bounds_kernel<<<1, 128>>>(batch);
    pool_kernel<<<NG, 256>>>();
    head1_kernel<<<NG, 256>>>(wl1, bl1);
    head2_kernel<<<NG, 64>>>(wl2, bl2);
    head3_kernel<<<1, 64>>>(wl3, bl3, out);
}

// round 16
// speedup vs baseline: 1.0903x; 1.0764x over previous
#include <cuda_runtime.h>
#include <cuda_bf16.h>
#include <cuda_fp16.h>
#include <math.h>
#include <stdint.h>

#define NN 10000
#define NE 320000
#define NG 64
#define DD 256

// ---------------- scratch (device globals; no allocation allowed) ----------------
__device__ __align__(16) float d_h[NN * DD];          // node features (current layer, fp32)
__device__ __align__(16) __half d_hh[NN * DD];        // fp16 mirror of h (gather source)
__device__ __align__(16) __nv_bfloat16 d_ah[NN * DD]; // (h+agg) bf16 hi
__device__ __align__(16) __nv_bfloat16 d_al[NN * DD]; // (h+agg) bf16 lo residual
__device__ __align__(16) __nv_bfloat16 d_whi[5 * 65536]; // W split hi, [l][n][k] K-major
__device__ __align__(16) __nv_bfloat16 d_wlo[5 * 65536]; // W split lo
__device__ int   d_rowstart[NN + 1];
__device__ int   d_cursor[NN];
__device__ int   d_csr[NE];
__device__ int   d_gstart[NG + 1];
__device__ __align__(16) float d_feat[NG * 2 * DD];
__device__ __align__(16) float d_h1[NG * DD];
__device__ __align__(16) float d_h2[NG * 64];
__device__ int   d_is64;

// ---------------- helpers ----------------
__device__ __forceinline__ uint32_t smem_u32(const void* p) {
    uint32_t a;
    asm("{ .reg .u64 t; cvta.to.shared.u64 t, %1; cvt.u32.u64 %0, t; }" : "=r"(a) : "l"(p));
    return a;
}
#define SW128(o) ((o) ^ (((o) >> 3) & 0x70))

__device__ __forceinline__ void ldm_x4(uint32_t* r, uint32_t addr) {
    asm volatile("ldmatrix.sync.aligned.m8n8.x4.shared.b16 {%0,%1,%2,%3}, [%4];"
        : "=r"(r[0]), "=r"(r[1]), "=r"(r[2]), "=r"(r[3]) : "r"(addr));
}
__device__ __forceinline__ void mma_bf16(float* c, const uint32_t* a, const uint32_t* b) {
    asm volatile("mma.sync.aligned.m16n8k16.row.col.f32.bf16.bf16.f32 "
        "{%0,%1,%2,%3}, {%4,%5,%6,%7}, {%8,%9}, {%0,%1,%2,%3};"
        : "+f"(c[0]), "+f"(c[1]), "+f"(c[2]), "+f"(c[3])
        : "r"(a[0]), "r"(a[1]), "r"(a[2]), "r"(a[3]), "r"(b[0]), "r"(b[1]));
}

// accumulate two fp16 values packed in a uint32 into fp32 accumulators
__device__ __forceinline__ void acc_h2(float& fa, float& fb, uint32_t u) {
    fa += __half2float(__ushort_as_half((unsigned short)(u & 0xFFFFu)));
    fb += __half2float(__ushort_as_half((unsigned short)(u >> 16)));
}

// index loader honoring detected dtype
__device__ __forceinline__ long long load_idx(const void* p, long long i, int is64) {
    if (is64) return ((const long long*)p)[i];
    return (long long)((const int*)p)[i];
}

// ---------------- dtype detection ----------------
__global__ void detect_kernel(const void* __restrict__ ei) {
    if (threadIdx.x == 0 && blockIdx.x == 0) {
        const long long* p = (const long long*)ei;
        int ok = 1;
        for (int i = 0; i < 64; i++) {
            long long v = p[i];
            if (v < 0 || v >= NN) { ok = 0; break; }
        }
        d_is64 = ok;
    }
}

// ---------------- init: x -> fp16 mirror ----------------
__global__ void xhalf_kernel(const float* __restrict__ x) {
    int i = blockIdx.x * blockDim.x + threadIdx.x;
    if (i < NN * DD / 4) {
        float4 v = ((const float4*)x)[i];
        __half2 h0 = __floats2half2_rn(v.x, v.y);
        __half2 h1 = __floats2half2_rn(v.z, v.w);
        ((__half2*)d_hh)[i * 2] = h0;
        ((__half2*)d_hh)[i * 2 + 1] = h1;
    }
}

__global__ void zero_rs_kernel() {
    int i = blockIdx.x * blockDim.x + threadIdx.x;
    if (i <= NN) d_rowstart[i] = 0;
}

// ---------------- weight split: Whi/Wlo[l][n][k] = split(W_l[k][n]) ----------------
__global__ void wsplit_kernel(const float* __restrict__ w0, const float* __restrict__ w1,
                              const float* __restrict__ w2, const float* __restrict__ w3,
                              const float* __restrict__ w4) {
    int idx = blockIdx.x * blockDim.x + threadIdx.x;
    if (idx >= 5 * 65536) return;
    int l = idx >> 16;
    int rem = idx & 65535;
    int n = rem >> 8;
    int k = rem & 255;
    const float* W = (l == 0) ? w0 : (l == 1) ? w1 : (l == 2) ? w2 : (l == 3) ? w3 : w4;
    float v = W[k * 256 + n];
    __nv_bfloat16 hi = __float2bfloat16(v);
    d_whi[idx] = hi;
    d_wlo[idx] = __float2bfloat16(v - __bfloat162float(hi));
}

// ---------------- CSR build (keyed by dst) ----------------
__global__ void hist_kernel(const void* __restrict__ ei) {
    int e = blockIdx.x * blockDim.x + threadIdx.x;
    if (e < NE) {
        int is64 = d_is64;
        int dn = (int)load_idx(ei, (long long)NE + e, is64);
        if (dn >= 0 && dn < NN) atomicAdd(&d_rowstart[dn + 1], 1);
    }
}

__global__ void scan_kernel() {
    __shared__ int sp[1024];
    const int CH = 10;
    int t = threadIdx.x;
    int base = t * CH;
    int v[CH];
    int run = 0;
#pragma unroll
    for (int j = 0; j < CH; j++) {
        int idx = base + j;
        int xv = (idx <= NN) ? d_rowstart[idx] : 0;
        run += xv;
        v[j] = run;
    }
    sp[t] = run;
    __syncthreads();
    for (int off = 1; off < 1024; off <<= 1) {
        int add = (t >= off) ? sp[t - off] : 0;
        __syncthreads();
        sp[t] += add;
        __syncthreads();
    }
    int excl = (t > 0) ? sp[t - 1] : 0;
#pragma unroll
    for (int j = 0; j < CH; j++) {
        int idx = base + j;
        if (idx <= NN) {
            int val = v[j] + excl;
            d_rowstart[idx] = val;
            if (idx < NN) d_cursor[idx] = val;
        }
    }
}

__global__ void fill_kernel(const void* __restrict__ ei) {
    int e = blockIdx.x * blockDim.x + threadIdx.x;
    if (e < NE) {
        int is64 = d_is64;
        int sn = (int)load_idx(ei, e, is64);
        int dn = (int)load_idx(ei, (long long)NE + e, is64);
        if (dn >= 0 && dn < NN && sn >= 0 && sn < NN) {
            int slot = atomicAdd(&d_cursor[dn], 1);
            if (slot < NE) d_csr[slot] = sn;
        }
    }
}

// ---------------- aggregation: split(h[i] + sum_{j in N(i)} h[j]) -> d_ah/d_al ----------------
// One warp per node (proven shape); gathers from the fp16 mirror (HALF the bytes),
// accumulates in fp32, edge loop unrolled x2. Each lane owns 8 half columns (16B).
__device__ __forceinline__ void split4_store(__nv_bfloat16* hp, __nv_bfloat16* lp, float4 v) {
    float f[4] = {v.x, v.y, v.z, v.w};
    __nv_bfloat16 h[4], l[4];
#pragma unroll
    for (int i = 0; i < 4; i++) {
        h[i] = __float2bfloat16(f[i]);
        l[i] = __float2bfloat16(f[i] - __bfloat162float(h[i]));
    }
    *(uint2*)hp = *(uint2*)h;
    *(uint2*)lp = *(uint2*)l;
}

__global__ void agg_kernel() {
    int warp = (blockIdx.x * blockDim.x + threadIdx.x) >> 5;
    int lane = threadIdx.x & 31;
    if (warp >= NN) return;
    int beg = d_rowstart[warp];
    int end = d_rowstart[warp + 1];
    float a0 = 0.f, a1 = 0.f, a2 = 0.f, a3 = 0.f;
    float a4 = 0.f, a5 = 0.f, a6 = 0.f, a7 = 0.f;
    {
        uint4 sv = ((const uint4*)(d_hh + (size_t)warp * DD))[lane];
        acc_h2(a0, a1, sv.x); acc_h2(a2, a3, sv.y);
        acc_h2(a4, a5, sv.z); acc_h2(a6, a7, sv.w);
    }
    int e = beg;
    for (; e + 2 <= end; e += 2) {
        int s0 = d_csr[e];
        int s1 = d_csr[e + 1];
        uint4 v0 = ((const uint4*)(d_hh + (size_t)s0 * DD))[lane];
        uint4 v1 = ((const uint4*)(d_hh + (size_t)s1 * DD))[lane];
        acc_h2(a0, a1, v0.x); acc_h2(a2, a3, v0.y);
        acc_h2(a4, a5, v0.z); acc_h2(a6, a7, v0.w);
        acc_h2(a0, a1, v1.x); acc_h2(a2, a3, v1.y);
        acc_h2(a4, a5, v1.z); acc_h2(a6, a7, v1.w);
    }
    for (; e < end; e++) {
        int s = d_csr[e];
        uint4 v0 = ((const uint4*)(d_hh + (size_t)s * DD))[lane];
        acc_h2(a0, a1, v0.x); acc_h2(a2, a3, v0.y);
        acc_h2(a4, a5, v0.z); acc_h2(a6, a7, v0.w);
    }
    size_t base = (size_t)warp * DD + lane * 8;
    split4_store(d_ah + base, d_al + base, make_float4(a0, a1, a2, a3));
    split4_store(d_ah + base + 4, d_al + base + 4, make_float4(a4, a5, a6, a7));
}

// ---------------- bf16 mma.sync GEMM: d_h = relu((Ah+Al)@(Wh+Wl) + b) ----------------
// CTA 128x128, 8 warps (4x2), warp tile 32x64. K=256 in 4 chunks of 64.
// SMEM tiles: 128 rows x 64 bf16 (128B rows, SW128 swizzle).
// Identical to the R12/R14 passing kernel except the epilogue also writes the
// fp16 mirror d_hh (two extra half2 stores).
#define SA_H 0
#define SA_L 16384
#define SB_H 32768
#define SB_L 49152
#define GEMM_SMEM 65536

__global__ void __launch_bounds__(256, 1) mma_gemm_kernel(const float* __restrict__ bias,
                                                          int layer) {
    extern __shared__ char smem[];
    const uint32_t sb = smem_u32(smem);
    const int tid = threadIdx.x, lane = tid & 31, wid = tid >> 5;
    const int m0 = blockIdx.x * 128, n0 = blockIdx.y * 128;
    const int wm = (wid & 3) * 32;   // warp row base within tile
    const int wn = (wid >> 2) * 64;  // warp col base within tile
    const __nv_bfloat16* wh = d_whi + (size_t)layer * 65536;
    const __nv_bfloat16* wl = d_wlo + (size_t)layer * 65536;

    float acc[2][8][4];
#pragma unroll
    for (int mt = 0; mt < 2; mt++)
#pragma unroll
        for (int nt = 0; nt < 8; nt++)
#pragma unroll
            for (int j = 0; j < 4; j++) acc[mt][nt][j] = 0.f;

    for (int c = 0; c < 4; c++) {
        // A tiles (hi/lo): 128 rows x 64 bf16 = 1024 uint4, 4 per thread
#pragma unroll
        for (int i = 0; i < 4; i++) {
            int idx = i * 256 + tid;
            int row = idx >> 3, q = idx & 7;
            int gr = m0 + row;
            uint4 vh = make_uint4(0, 0, 0, 0), vl = make_uint4(0, 0, 0, 0);
            if (gr < NN) {
                vh = *(const uint4*)(d_ah + (size_t)gr * 256 + c * 64 + q * 8);
                vl = *(const uint4*)(d_al + (size_t)gr * 256 + c * 64 + q * 8);
            }
            uint32_t off = SW128((uint32_t)(row * 128 + q * 16));
            *(uint4*)(smem + SA_H + off) = vh;
            *(uint4*)(smem + SA_L + off) = vl;
        }
        // B tiles (hi/lo): rows n0..n0+127 of W[n][k]
#pragma unroll
        for (int i = 0; i < 4; i++) {
            int idx = i * 256 + tid;
            int row = idx >> 3, q = idx & 7;
            int gn = n0 + row;
            uint4 vh = *(const uint4*)(wh + (size_t)gn * 256 + c * 64 + q * 8);
            uint4 vl = *(const uint4*)(wl + (size_t)gn * 256 + c * 64 + q * 8);
            uint32_t off = SW128((uint32_t)(row * 128 + q * 16));
            *(uint4*)(smem + SB_H + off) = vh;
            *(uint4*)(smem + SB_L + off) = vl;
        }
        __syncthreads();

#pragma unroll
        for (int ks = 0; ks < 4; ks++) {
            const int k0 = ks * 16;
            uint32_t ah[2][4], al[2][4], bh[4][4], bl[4][4];
#pragma unroll
            for (int mt = 0; mt < 2; mt++) {
                int r = wm + mt * 16 + (lane & 15);
                int kb = (k0 + ((lane >> 4) << 3)) * 2;
                uint32_t off = SW128((uint32_t)(r * 128 + kb));
                ldm_x4(ah[mt], sb + SA_H + off);
                ldm_x4(al[mt], sb + SA_L + off);
            }
#pragma unroll
            for (int np = 0; np < 4; np++) {
                int r = wn + np * 16 + ((lane >> 4) << 3) + (lane & 7);
                int kb = (k0 + (((lane >> 3) & 1) << 3)) * 2;
                uint32_t off = SW128((uint32_t)(r * 128 + kb));
                ldm_x4(bh[np], sb + SB_H + off);
                ldm_x4(bl[np], sb + SB_L + off);
            }
#pragma unroll
            for (int mt = 0; mt < 2; mt++)
#pragma unroll
                for (int nt = 0; nt < 8; nt++) {
                    const uint32_t* B0 = &bh[nt >> 1][(nt & 1) * 2];
                    const uint32_t* B1 = &bl[nt >> 1][(nt & 1) * 2];
                    mma_bf16(acc[mt][nt], ah[mt], B0);
                    mma_bf16(acc[mt][nt], ah[mt], B1);
                    mma_bf16(acc[mt][nt], al[mt], B0);
                }
        }
        __syncthreads();
    }

    // epilogue: c0,c1 at (row t/4, col (t%4)*2), c2,c3 at row t/4+8
    const int tq = lane >> 2;
    const int tr = (lane & 3) * 2;
#pragma unroll
    for (int mt = 0; mt < 2; mt++)
#pragma unroll
        for (int nt = 0; nt < 8; nt++) {
            int gc = n0 + wn + nt * 8 + tr;
            float2 bv = *(const float2*)(bias + gc);
            int gr0 = m0 + wm + mt * 16 + tq;
            if (gr0 < NN) {
                float2 o;
                o.x = fmaxf(acc[mt][nt][0] + bv.x, 0.f);
                o.y = fmaxf(acc[mt][nt][1] + bv.y, 0.f);
                *(float2*)(d_h + (size_t)gr0 * 256 + gc) = o;
                *(__half2*)(d_hh + (size_t)gr0 * 256 + gc) = __floats2half2_rn(o.x, o.y);
            }
            int gr1 = gr0 + 8;
            if (gr1 < NN) {
                float2 o;
                o.x = fmaxf(acc[mt][nt][2] + bv.x, 0.f);
                o.y = fmaxf(acc[mt][nt][3] + bv.y, 0.f);
                *(float2*)(d_h + (size_t)gr1 * 256 + gc) = o;
                *(__half2*)(d_hh + (size_t)gr1 * 256 + gc) = __floats2half2_rn(o.x, o.y);
            }
        }
}

// ---------------- pooling ----------------
__global__ void bounds_kernel(const void* __restrict__ batch) {
    int g = threadIdx.x;
    if (g > NG) return;
    int is64 = d_is64;
    int lo = 0, hi = NN;
    while (lo < hi) {
        int mid = (lo + hi) >> 1;
        if (load_idx(batch, mid, is64) < (long long)g) lo = mid + 1;
        else hi = mid;
    }
    d_gstart[g] = lo;
}

__global__ void pool_kernel() {
    int g = blockIdx.x;
    int c = threadIdx.x;
    int s = d_gstart[g], e = d_gstart[g + 1];
    float sum = 0.f;
    float mx = -INFINITY;
    for (int i = s; i < e; i++) {
        float v = d_h[(size_t)i * DD + c];
        sum += v;
        mx = fmaxf(mx, v);
    }
    int cnt = e - s;
    float denom = fmaxf((float)cnt, 1.0f);
    d_feat[g * 512 + c] = sum / denom;
    d_feat[g * 512 + 256 + c] = mx;
}

// ---------------- head MLP ----------------
__global__ void head1_kernel(const float* __restrict__ w, const float* __restrict__ b) {
    __shared__ float s[512];
    int g = blockIdx.x;
    for (int i = threadIdx.x; i < 512; i += 256) s[i] = d_feat[g * 512 + i];
    __syncthreads();
    int t = threadIdx.x;
    float acc = b[t];
    for (int k = 0; k < 512; k++) acc = fmaf(s[k], w[k * 256 + t], acc);
    d_h1[g * 256 + t] = fmaxf(acc, 0.f);
}

__global__ void head2_kernel(const float* __restrict__ w, const float* __restrict__ b) {
    __shared__ float s[256];
    int g = blockIdx.x;
    for (int i = threadIdx.x; i < 256; i += 64) s[i] = d_h1[g * 256 + i];
    __syncthreads();
    int t = threadIdx.x;
    float acc = b[t];
    for (int k = 0; k < 256; k++) acc = fmaf(s[k], w[k * 64 + t], acc);
    d_h2[g * 64 + t] = fmaxf(acc, 0.f);
}

__global__ void head3_kernel(const float* __restrict__ w, const float* __restrict__ b,
                             float* __restrict__ out) {
    int g = threadIdx.x;
    if (g >= NG) return;
    float acc = b[0];
    for (int k = 0; k < 64; k++) acc = fmaf(d_h2[g * 64 + k], w[k], acc);
    out[g] = 1.0f / (1.0f + expf(-acc));
}

// ---------------- launch ----------------
extern "C" void kernel_launch(void* const* d_in, const int* in_sizes, int n_in,
                              void* d_out, int out_size) {
    const float* x = (const float*)d_in[0];
    const void* ei = d_in[1];
    const void* batch = d_in[2];
    const float* w[5];
    const float* b[5];
    for (int i = 0; i < 5; i++) {
        w[i] = (const float*)d_in[3 + 2 * i];
        b[i] = (const float*)d_in[4 + 2 * i];
    }
    const float* wl1 = (const float*)d_in[13];
    const float* bl1 = (const float*)d_in[14];
    const float* wl2 = (const float*)d_in[15];
    const float* bl2 = (const float*)d_in[16];
    const float* wl3 = (const float*)d_in[17];
    const float* bl3 = (const float*)d_in[18];
    float* out = (float*)d_out;

    static int configured = 0;
    if (!configured) {
        cudaFuncSetAttribute(mma_gemm_kernel, cudaFuncAttributeMaxDynamicSharedMemorySize,
                             GEMM_SMEM);
        configured = 1;
    }

    detect_kernel<<<1, 32>>>(ei);
    xhalf_kernel<<<(NN * DD / 4 + 255) / 256, 256>>>(x);
    zero_rs_kernel<<<(NN + 1 + 255) / 256, 256>>>();
    hist_kernel<<<(NE + 255) / 256, 256>>>(ei);
    scan_kernel<<<1, 1024>>>();
    fill_kernel<<<(NE + 255) / 256, 256>>>(ei);
    wsplit_kernel<<<(5 * 65536 + 255) / 256, 256>>>(w[0], w[1], w[2], w[3], w[4]);

    for (int l = 0; l < 5; l++) {
        agg_kernel<<<(NN * 32 + 255) / 256, 256>>>();
        mma_gemm_kernel<<<dim3((NN + 127) / 128, 2), 256, GEMM_SMEM>>>(b[l], l);
    }

    bounds_kernel<<<1, 128>>>(batch);
    pool_kernel<<<NG, 256>>>();
    head1_kernel<<<NG, 256>>>(wl1, bl1);
    head2_kernel<<<NG, 64>>>(wl2, bl2);
    head3_kernel<<<1, 64>>>(wl3, bl3, out);
}

// round 17
// speedup vs baseline: 1.1043x; 1.0129x over previous
#include <cuda_runtime.h>
#include <cuda_bf16.h>
#include <cuda_fp16.h>
#include <math.h>
#include <stdint.h>

#define NN 10000
#define NE 320000
#define NG 64
#define DD 256

// ---------------- scratch (device globals; no allocation allowed) ----------------
__device__ __align__(16) float d_h[NN * DD];          // node features (current layer, fp32)
__device__ __align__(16) __half d_hh[NN * DD];        // fp16 mirror of h (gather source)
__device__ __align__(16) __nv_bfloat16 d_ah[NN * DD]; // (h+agg) bf16 hi
__device__ __align__(16) __nv_bfloat16 d_al[NN * DD]; // (h+agg) bf16 lo residual
__device__ __align__(16) __nv_bfloat16 d_whi[5 * 65536]; // W split hi, [l][n][k] K-major
__device__ __align__(16) __nv_bfloat16 d_wlo[5 * 65536]; // W split lo
__device__ int   d_rowstart[NN + 1];
__device__ int   d_cursor[NN];
__device__ int   d_csr[NE];
__device__ int   d_gstart[NG + 1];
__device__ __align__(16) float d_feat[NG * 2 * DD];
__device__ __align__(16) float d_h1[NG * DD];
__device__ __align__(16) float d_h2[NG * 64];
__device__ int   d_is64;

// ---------------- helpers ----------------
__device__ __forceinline__ uint32_t smem_u32(const void* p) {
    uint32_t a;
    asm("{ .reg .u64 t; cvta.to.shared.u64 t, %1; cvt.u32.u64 %0, t; }" : "=r"(a) : "l"(p));
    return a;
}
#define SW128(o) ((o) ^ (((o) >> 3) & 0x70))

__device__ __forceinline__ void ldm_x4(uint32_t* r, uint32_t addr) {
    asm volatile("ldmatrix.sync.aligned.m8n8.x4.shared.b16 {%0,%1,%2,%3}, [%4];"
        : "=r"(r[0]), "=r"(r[1]), "=r"(r[2]), "=r"(r[3]) : "r"(addr));
}
__device__ __forceinline__ void mma_bf16(float* c, const uint32_t* a, const uint32_t* b) {
    asm volatile("mma.sync.aligned.m16n8k16.row.col.f32.bf16.bf16.f32 "
        "{%0,%1,%2,%3}, {%4,%5,%6,%7}, {%8,%9}, {%0,%1,%2,%3};"
        : "+f"(c[0]), "+f"(c[1]), "+f"(c[2]), "+f"(c[3])
        : "r"(a[0]), "r"(a[1]), "r"(a[2]), "r"(a[3]), "r"(b[0]), "r"(b[1]));
}

// accumulate two fp16 values packed in a uint32 into fp32 accumulators
__device__ __forceinline__ void acc_h2(float& fa, float& fb, uint32_t u) {
    fa += __half2float(__ushort_as_half((unsigned short)(u & 0xFFFFu)));
    fb += __half2float(__ushort_as_half((unsigned short)(u >> 16)));
}
__device__ __forceinline__ void acc_v4(float& a0, float& a1, float& a2, float& a3,
                                       float& a4, float& a5, float& a6, float& a7,
                                       uint4 v) {
    acc_h2(a0, a1, v.x); acc_h2(a2, a3, v.y);
    acc_h2(a4, a5, v.z); acc_h2(a6, a7, v.w);
}

// index loader honoring detected dtype
__device__ __forceinline__ long long load_idx(const void* p, long long i, int is64) {
    if (is64) return ((const long long*)p)[i];
    return (long long)((const int*)p)[i];
}

// ---------------- dtype detection ----------------
__global__ void detect_kernel(const void* __restrict__ ei) {
    if (threadIdx.x == 0 && blockIdx.x == 0) {
        const long long* p = (const long long*)ei;
        int ok = 1;
        for (int i = 0; i < 64; i++) {
            long long v = p[i];
            if (v < 0 || v >= NN) { ok = 0; break; }
        }
        d_is64 = ok;
    }
}

// ---------------- init: x -> fp16 mirror ----------------
__global__ void xhalf_kernel(const float* __restrict__ x) {
    int i = blockIdx.x * blockDim.x + threadIdx.x;
    if (i < NN * DD / 4) {
        float4 v = ((const float4*)x)[i];
        __half2 h0 = __floats2half2_rn(v.x, v.y);
        __half2 h1 = __floats2half2_rn(v.z, v.w);
        ((__half2*)d_hh)[i * 2] = h0;
        ((__half2*)d_hh)[i * 2 + 1] = h1;
    }
}

__global__ void zero_rs_kernel() {
    int i = blockIdx.x * blockDim.x + threadIdx.x;
    if (i <= NN) d_rowstart[i] = 0;
}

// ---------------- weight split: Whi/Wlo[l][n][k] = split(W_l[k][n]) ----------------
__global__ void wsplit_kernel(const float* __restrict__ w0, const float* __restrict__ w1,
                              const float* __restrict__ w2, const float* __restrict__ w3,
                              const float* __restrict__ w4) {
    int idx = blockIdx.x * blockDim.x + threadIdx.x;
    if (idx >= 5 * 65536) return;
    int l = idx >> 16;
    int rem = idx & 65535;
    int n = rem >> 8;
    int k = rem & 255;
    const float* W = (l == 0) ? w0 : (l == 1) ? w1 : (l == 2) ? w2 : (l == 3) ? w3 : w4;
    float v = W[k * 256 + n];
    __nv_bfloat16 hi = __float2bfloat16(v);
    d_whi[idx] = hi;
    d_wlo[idx] = __float2bfloat16(v - __bfloat162float(hi));
}

// ---------------- CSR build (keyed by dst) ----------------
__global__ void hist_kernel(const void* __restrict__ ei) {
    int e = blockIdx.x * blockDim.x + threadIdx.x;
    if (e < NE) {
        int is64 = d_is64;
        int dn = (int)load_idx(ei, (long long)NE + e, is64);
        if (dn >= 0 && dn < NN) atomicAdd(&d_rowstart[dn + 1], 1);
    }
}

__global__ void scan_kernel() {
    __shared__ int sp[1024];
    const int CH = 10;
    int t = threadIdx.x;
    int base = t * CH;
    int v[CH];
    int run = 0;
#pragma unroll
    for (int j = 0; j < CH; j++) {
        int idx = base + j;
        int xv = (idx <= NN) ? d_rowstart[idx] : 0;
        run += xv;
        v[j] = run;
    }
    sp[t] = run;
    __syncthreads();
    for (int off = 1; off < 1024; off <<= 1) {
        int add = (t >= off) ? sp[t - off] : 0;
        __syncthreads();
        sp[t] += add;
        __syncthreads();
    }
    int excl = (t > 0) ? sp[t - 1] : 0;
#pragma unroll
    for (int j = 0; j < CH; j++) {
        int idx = base + j;
        if (idx <= NN) {
            int val = v[j] + excl;
            d_rowstart[idx] = val;
            if (idx < NN) d_cursor[idx] = val;
        }
    }
}

__global__ void fill_kernel(const void* __restrict__ ei) {
    int e = blockIdx.x * blockDim.x + threadIdx.x;
    if (e < NE) {
        int is64 = d_is64;
        int sn = (int)load_idx(ei, e, is64);
        int dn = (int)load_idx(ei, (long long)NE + e, is64);
        if (dn >= 0 && dn < NN && sn >= 0 && sn < NN) {
            int slot = atomicAdd(&d_cursor[dn], 1);
            if (slot < NE) d_csr[slot] = sn;
        }
    }
}

// ---------------- aggregation: split(h[i] + sum_{j in N(i)} h[j]) -> d_ah/d_al ----------------
// One warp per node; gathers from the fp16 mirror, fp32 accum, edge loop unrolled x4
// (4 independent uint4 loads in flight per lane). Each lane owns 8 half columns.
__device__ __forceinline__ void split4_store(__nv_bfloat16* hp, __nv_bfloat16* lp, float4 v) {
    float f[4] = {v.x, v.y, v.z, v.w};
    __nv_bfloat16 h[4], l[4];
#pragma unroll
    for (int i = 0; i < 4; i++) {
        h[i] = __float2bfloat16(f[i]);
        l[i] = __float2bfloat16(f[i] - __bfloat162float(h[i]));
    }
    *(uint2*)hp = *(uint2*)h;
    *(uint2*)lp = *(uint2*)l;
}

__global__ void agg_kernel() {
    int warp = (blockIdx.x * blockDim.x + threadIdx.x) >> 5;
    int lane = threadIdx.x & 31;
    if (warp >= NN) return;
    int beg = d_rowstart[warp];
    int end = d_rowstart[warp + 1];
    float a0 = 0.f, a1 = 0.f, a2 = 0.f, a3 = 0.f;
    float a4 = 0.f, a5 = 0.f, a6 = 0.f, a7 = 0.f;
    {
        uint4 sv = ((const uint4*)(d_hh + (size_t)warp * DD))[lane];
        acc_v4(a0, a1, a2, a3, a4, a5, a6, a7, sv);
    }
    int e = beg;
    for (; e + 4 <= end; e += 4) {
        int s0 = d_csr[e];
        int s1 = d_csr[e + 1];
        int s2 = d_csr[e + 2];
        int s3 = d_csr[e + 3];
        uint4 v0 = ((const uint4*)(d_hh + (size_t)s0 * DD))[lane];
        uint4 v1 = ((const uint4*)(d_hh + (size_t)s1 * DD))[lane];
        uint4 v2 = ((const uint4*)(d_hh + (size_t)s2 * DD))[lane];
        uint4 v3 = ((const uint4*)(d_hh + (size_t)s3 * DD))[lane];
        acc_v4(a0, a1, a2, a3, a4, a5, a6, a7, v0);
        acc_v4(a0, a1, a2, a3, a4, a5, a6, a7, v1);
        acc_v4(a0, a1, a2, a3, a4, a5, a6, a7, v2);
        acc_v4(a0, a1, a2, a3, a4, a5, a6, a7, v3);
    }
    for (; e < end; e++) {
        int s = d_csr[e];
        uint4 v0 = ((const uint4*)(d_hh + (size_t)s * DD))[lane];
        acc_v4(a0, a1, a2, a3, a4, a5, a6, a7, v0);
    }
    size_t base = (size_t)warp * DD + lane * 8;
    split4_store(d_ah + base, d_al + base, make_float4(a0, a1, a2, a3));
    split4_store(d_ah + base + 4, d_al + base + 4, make_float4(a4, a5, a6, a7));
}

// ---------------- bf16 mma.sync GEMM: d_h = relu((Ah+Al)@(Wh+Wl) + b) ----------------
// CTA 128x128, 8 warps (4x2), warp tile 32x64. K=256 in 4 chunks of 64.
// SMEM tiles: 128 rows x 64 bf16 (128B rows, SW128 swizzle).
// Identical to the R16 passing kernel (epilogue also writes the fp16 mirror).
#define SA_H 0
#define SA_L 16384
#define SB_H 32768
#define SB_L 49152
#define GEMM_SMEM 65536

__global__ void __launch_bounds__(256, 1) mma_gemm_kernel(const float* __restrict__ bias,
                                                          int layer) {
    extern __shared__ char smem[];
    const uint32_t sb = smem_u32(smem);
    const int tid = threadIdx.x, lane = tid & 31, wid = tid >> 5;
    const int m0 = blockIdx.x * 128, n0 = blockIdx.y * 128;
    const int wm = (wid & 3) * 32;   // warp row base within tile
    const int wn = (wid >> 2) * 64;  // warp col base within tile
    const __nv_bfloat16* wh = d_whi + (size_t)layer * 65536;
    const __nv_bfloat16* wl = d_wlo + (size_t)layer * 65536;

    float acc[2][8][4];
#pragma unroll
    for (int mt = 0; mt < 2; mt++)
#pragma unroll
        for (int nt = 0; nt < 8; nt++)
#pragma unroll
            for (int j = 0; j < 4; j++) acc[mt][nt][j] = 0.f;

    for (int c = 0; c < 4; c++) {
        // A tiles (hi/lo): 128 rows x 64 bf16 = 1024 uint4, 4 per thread
#pragma unroll
        for (int i = 0; i < 4; i++) {
            int idx = i * 256 + tid;
            int row = idx >> 3, q = idx & 7;
            int gr = m0 + row;
            uint4 vh = make_uint4(0, 0, 0, 0), vl = make_uint4(0, 0, 0, 0);
            if (gr < NN) {
                vh = *(const uint4*)(d_ah + (size_t)gr * 256 + c * 64 + q * 8);
                vl = *(const uint4*)(d_al + (size_t)gr * 256 + c * 64 + q * 8);
            }
            uint32_t off = SW128((uint32_t)(row * 128 + q * 16));
            *(uint4*)(smem + SA_H + off) = vh;
            *(uint4*)(smem + SA_L + off) = vl;
        }
        // B tiles (hi/lo): rows n0..n0+127 of W[n][k]
#pragma unroll
        for (int i = 0; i < 4; i++) {
            int idx = i * 256 + tid;
            int row = idx >> 3, q = idx & 7;
            int gn = n0 + row;
            uint4 vh = *(const uint4*)(wh + (size_t)gn * 256 + c * 64 + q * 8);
            uint4 vl = *(const uint4*)(wl + (size_t)gn * 256 + c * 64 + q * 8);
            uint32_t off = SW128((uint32_t)(row * 128 + q * 16));
            *(uint4*)(smem + SB_H + off) = vh;
            *(uint4*)(smem + SB_L + off) = vl;
        }
        __syncthreads();

#pragma unroll
        for (int ks = 0; ks < 4; ks++) {
            const int k0 = ks * 16;
            uint32_t ah[2][4], al[2][4], bh[4][4], bl[4][4];
#pragma unroll
            for (int mt = 0; mt < 2; mt++) {
                int r = wm + mt * 16 + (lane & 15);
                int kb = (k0 + ((lane >> 4) << 3)) * 2;
                uint32_t off = SW128((uint32_t)(r * 128 + kb));
                ldm_x4(ah[mt], sb + SA_H + off);
                ldm_x4(al[mt], sb + SA_L + off);
            }
#pragma unroll
            for (int np = 0; np < 4; np++) {
                int r = wn + np * 16 + ((lane >> 4) << 3) + (lane & 7);
                int kb = (k0 + (((lane >> 3) & 1) << 3)) * 2;
                uint32_t off = SW128((uint32_t)(r * 128 + kb));
                ldm_x4(bh[np], sb + SB_H + off);
                ldm_x4(bl[np], sb + SB_L + off);
            }
#pragma unroll
            for (int mt = 0; mt < 2; mt++)
#pragma unroll
                for (int nt = 0; nt < 8; nt++) {
                    const uint32_t* B0 = &bh[nt >> 1][(nt & 1) * 2];
                    const uint32_t* B1 = &bl[nt >> 1][(nt & 1) * 2];
                    mma_bf16(acc[mt][nt], ah[mt], B0);
                    mma_bf16(acc[mt][nt], ah[mt], B1);
                    mma_bf16(acc[mt][nt], al[mt], B0);
                }
        }
        __syncthreads();
    }

    // epilogue: c0,c1 at (row t/4, col (t%4)*2), c2,c3 at row t/4+8
    const int tq = lane >> 2;
    const int tr = (lane & 3) * 2;
#pragma unroll
    for (int mt = 0; mt < 2; mt++)
#pragma unroll
        for (int nt = 0; nt < 8; nt++) {
            int gc = n0 + wn + nt * 8 + tr;
            float2 bv = *(const float2*)(bias + gc);
            int gr0 = m0 + wm + mt * 16 + tq;
            if (gr0 < NN) {
                float2 o;
                o.x = fmaxf(acc[mt][nt][0] + bv.x, 0.f);
                o.y = fmaxf(acc[mt][nt][1] + bv.y, 0.f);
                *(float2*)(d_h + (size_t)gr0 * 256 + gc) = o;
                *(__half2*)(d_hh + (size_t)gr0 * 256 + gc) = __floats2half2_rn(o.x, o.y);
            }
            int gr1 = gr0 + 8;
            if (gr1 < NN) {
                float2 o;
                o.x = fmaxf(acc[mt][nt][2] + bv.x, 0.f);
                o.y = fmaxf(acc[mt][nt][3] + bv.y, 0.f);
                *(float2*)(d_h + (size_t)gr1 * 256 + gc) = o;
                *(__half2*)(d_hh + (size_t)gr1 * 256 + gc) = __floats2half2_rn(o.x, o.y);
            }
        }
}

// ---------------- pooling ----------------
__global__ void bounds_kernel(const void* __restrict__ batch) {
    int g = threadIdx.x;
    if (g > NG) return;
    int is64 = d_is64;
    int lo = 0, hi = NN;
    while (lo < hi) {
        int mid = (lo + hi) >> 1;
        if (load_idx(batch, mid, is64) < (long long)g) lo = mid + 1;
        else hi = mid;
    }
    d_gstart[g] = lo;
}

__global__ void pool_kernel() {
    int g = blockIdx.x;
    int c = threadIdx.x;
    int s = d_gstart[g], e = d_gstart[g + 1];
    float sum = 0.f;
    float mx = -INFINITY;
    for (int i = s; i < e; i++) {
        float v = d_h[(size_t)i * DD + c];
        sum += v;
        mx = fmaxf(mx, v);
    }
    int cnt = e - s;
    float denom = fmaxf((float)cnt, 1.0f);
    d_feat[g * 512 + c] = sum / denom;
    d_feat[g * 512 + 256 + c] = mx;
}

// ---------------- head MLP ----------------
__global__ void head1_kernel(const float* __restrict__ w, const float* __restrict__ b) {
    __shared__ float s[512];
    int g = blockIdx.x;
    for (int i = threadIdx.x; i < 512; i += 256) s[i] = d_feat[g * 512 + i];
    __syncthreads();
    int t = threadIdx.x;
    float acc = b[t];
    for (int k = 0; k < 512; k++) acc = fmaf(s[k], w[k * 256 + t], acc);
    d_h1[g * 256 + t] = fmaxf(acc, 0.f);
}

__global__ void head2_kernel(const float* __restrict__ w, const float* __restrict__ b) {
    __shared__ float s[256];
    int g = blockIdx.x;
    for (int i = threadIdx.x; i < 256; i += 64) s[i] = d_h1[g * 256 + i];
    __syncthreads();
    int t = threadIdx.x;
    float acc = b[t];
    for (int k = 0; k < 256; k++) acc = fmaf(s[k], w[k * 64 + t], acc);
    d_h2[g * 64 + t] = fmaxf(acc, 0.f);
}

__global__ void head3_kernel(const float* __restrict__ w, const float* __restrict__ b,
                             float* __restrict__ out) {
    int g = threadIdx.x;
    if (g >= NG) return;
    float acc = b[0];
    for (int k = 0; k < 64; k++) acc = fmaf(d_h2[g * 64 + k], w[k], acc);
    out[g] = 1.0f / (1.0f + expf(-acc));
}

// ---------------- launch ----------------
extern "C" void kernel_launch(void* const* d_in, const int* in_sizes, int n_in,
                              void* d_out, int out_size) {
    const float* x = (const float*)d_in[0];
    const void* ei = d_in[1];
    const void* batch = d_in[2];
    const float* w[5];
    const float* b[5];
    for (int i = 0; i < 5; i++) {
        w[i] = (const float*)d_in[3 + 2 * i];
        b[i] = (const float*)d_in[4 + 2 * i];
    }
    const float* wl1 = (const float*)d_in[13];
    const float* bl1 = (const float*)d_in[14];
    const float* wl2 = (const float*)d_in[15];
    const float* bl2 = (const float*)d_in[16];
    const float* wl3 = (const float*)d_in[17];
    const float* bl3 = (const float*)d_in[18];
    float* out = (float*)d_out;

    static int configured = 0;
    if (!configured) {
        cudaFuncSetAttribute(mma_gemm_kernel, cudaFuncAttributeMaxDynamicSharedMemorySize,
                             GEMM_SMEM);
        configured = 1;
    }

    detect_kernel<<<1, 32>>>(ei);
    xhalf_kernel<<<(NN * DD / 4 + 255) / 256, 256>>>(x);
    zero_rs_kernel<<<(NN + 1 + 255) / 256, 256>>>();
    hist_kernel<<<(NE + 255) / 256, 256>>>(ei);
    scan_kernel<<<1, 1024>>>();
    fill_kernel<<<(NE + 255) / 256, 256>>>(ei);
    wsplit_kernel<<<(5 * 65536 + 255) / 256, 256>>>(w[0], w[1], w[2], w[3], w[4]);

    for (int l = 0; l < 5; l++) {
        agg_kernel<<<(NN * 32 + 255) / 256, 256>>>();
        mma_gemm_kernel<<<dim3((NN + 127) / 128, 2), 256, GEMM_SMEM>>>(b[l], l);
    }

    bounds_kernel<<<1, 128>>>(batch);
    pool_kernel<<<NG, 256>>>();
    head1_kernel<<<NG, 256>>>(wl1, bl1);
    head2_kernel<<<NG, 64>>>(wl2, bl2);
    head3_kernel<<<1, 64>>>(wl3, bl3, out);
}